// round 5
// baseline (speedup 1.0000x reference)
#include <cuda_runtime.h>
#include <math.h>

#define THREADS 256
#define NWARP 8
#define PB 12

typedef unsigned long long u64;

// shared layout (floats)
#define OFF_W1KP 0          // [64][128][2]  fwd:  {W1[j][2k2], W1[j][2k2+1]}
#define OFF_W1JP 16384      // [64][128][2]  bwd:  {30*Wo[j]*W1[j][k]} pairs over j
#define OFF_W0KP 32768      // [10][128][2]  fwd L0 (input 19 zero-padded to 20)
#define OFF_W0T  35328      // [19][128]     bwd-fused, pre-scaled by 30
#define OFF_B0   37760
#define OFF_B1   37888
#define OFF_WO   38016
#define OFF_STAGE 38144
#define WARP_STAGE 2352     // buf 1536 | hs 240 | dEs 576
#define SMEM_FLOATS (OFF_STAGE + NWARP * WARP_STAGE)

__device__ __forceinline__ float shx(float v, int m) {
    return __shfl_xor_sync(0xFFFFFFFFu, v, m);
}
__device__ __forceinline__ void ffma2(u64 &d, u64 a, u64 b) {
    asm("fma.rn.f32x2 %0, %1, %2, %0;" : "+l"(d) : "l"(a), "l"(b));
}
__device__ __forceinline__ float hadd2(u64 v) {
    return __uint_as_float((unsigned)v) + __uint_as_float((unsigned)(v >> 32));
}

__global__ void __launch_bounds__(THREADS, 1)
neural_sdf_kernel(const float* __restrict__ pos,
                  const float* __restrict__ grid,
                  const float* __restrict__ W0g,
                  const float* __restrict__ b0g,
                  const float* __restrict__ W1g,
                  const float* __restrict__ b1g,
                  const float* __restrict__ Wog,
                  const float* __restrict__ bog,
                  float* __restrict__ out,
                  int n_pts)
{
    extern __shared__ float sm[];
    float* W1kp = sm + OFF_W1KP;
    float* W1jp = sm + OFF_W1JP;
    float* W0kp = sm + OFF_W0KP;
    float* W0T  = sm + OFF_W0T;
    float* b0s  = sm + OFF_B0;
    float* b1s  = sm + OFF_B1;
    float* Wos  = sm + OFF_WO;

    const int tid = threadIdx.x;

    // ---- cooperative weight preload ----
    for (int idx = tid; idx < 16384; idx += THREADS) {
        int hi = idx >> 8, rem = idx & 255, m = rem >> 1, c = rem & 1;
        // forward: W1kp[k2][j][c] = W1[j][2*k2+c]
        W1kp[idx] = W1g[m * 128 + (hi * 2 + c)];
        // backward: W1jp[j2][k][c] = 30*Wo[j]*W1[j][k],  j = 2*hi+c
        int j = hi * 2 + c;
        W1jp[idx] = 30.0f * Wog[j] * W1g[j * 128 + m];
    }
    for (int idx = tid; idx < 2560; idx += THREADS) {
        int i2 = idx >> 8, rem = idx & 255, j = rem >> 1, c = rem & 1;
        int i = i2 * 2 + c;
        W0kp[idx] = (i < 19) ? W0g[j * 19 + i] : 0.0f;
    }
    for (int idx = tid; idx < 128 * 19; idx += THREADS) {
        int j = idx / 19;
        int i = idx - j * 19;
        W0T[(i << 7) + j] = 30.0f * W0g[idx];   // derivative 30 folded in
    }
    if (tid < 128) {
        b0s[tid] = b0g[tid];
        b1s[tid] = b1g[tid];
        Wos[tid] = Wog[tid];
    }
    __syncthreads();

    const int w    = tid >> 5;
    const int lane = tid & 31;
    float* buf = sm + OFF_STAGE + w * WARP_STAGE;  // a0 then cos1 [p][128]
    float* hs  = buf + PB * 128;                    // [p][20]
    float* dEs = hs + PB * 20;                      // [p][48]: dx16|dy16|dz16

    const int e    = lane & 15;
    const int half = lane >> 4;
    const int j0   = lane << 2;

    float b0a[4], b1a[4], woa[4];
    *(float4*)b0a = *(const float4*)(b0s + j0);
    *(float4*)b1a = *(const float4*)(b1s + j0);
    *(float4*)woa = *(const float4*)(Wos + j0);
    const float bo_r = __ldg(bog);

    const int gw = blockIdx.x * NWARP + w;
    const int nw = gridDim.x * NWARP;

    for (int n0 = gw * PB; n0 < n_pts; n0 += nw * PB) {

        // ================= gather: PB points =================
        #pragma unroll
        for (int p = 0; p < PB; p++) {
            int n = n0 + p;
            int nc = (n < n_pts) ? n : (n_pts - 1);
            float px = fmaf(__ldg(pos + 3 * nc + 0), 0.5f, 0.5f);
            float py = fmaf(__ldg(pos + 3 * nc + 1), 0.5f, 0.5f);
            float pz = fmaf(__ldg(pos + 3 * nc + 2), 0.5f, 0.5f);
            float xx = px * 127.0f, xy = py * 127.0f, xz = pz * 127.0f;
            int ix = min(126, max(0, (int)floorf(xx)));
            int iy = min(126, max(0, (int)floorf(xy)));
            int iz = min(126, max(0, (int)floorf(xz)));
            float fx = xx - (float)ix;
            float fy = xy - (float)iy;
            float fz = xz - (float)iz;
            int base = ((ix << 7) + iy) * 128 + iz;

            float emb = 0.f, dex = 0.f, dey = 0.f, dez = 0.f;
            #pragma unroll
            for (int cc = 0; cc < 4; cc++) {
                int c  = (half << 2) + cc;
                int dx = (c >> 2) & 1, dy = (c >> 1) & 1, dz = c & 1;
                float wx = dx ? fx : 1.0f - fx;
                float wy = dy ? fy : 1.0f - fy;
                float wz = dz ? fz : 1.0f - fz;
                int gi = base + (dx << 14) + (dy << 7) + dz;
                float g = __ldg(grid + (gi << 4) + e);
                float wyz = wy * wz, wxz = wx * wz, wxy = wx * wy;
                emb = fmaf(g, wx * wyz, emb);
                float gyz = g * wyz, gxz = g * wxz, gxy = g * wxy;
                dex += dx ? gyz : -gyz;
                dey += dy ? gxz : -gxz;
                dez += dz ? gxy : -gxy;
            }
            emb += shx(emb, 16);
            dex += shx(dex, 16);
            dey += shx(dey, 16);
            dez += shx(dez, 16);

            if (lane < 16) {
                hs[p * 20 + e]       = emb;
                dEs[p * 48 + e]      = dex * 127.0f;
                dEs[p * 48 + 16 + e] = dey * 127.0f;
                dEs[p * 48 + 32 + e] = dez * 127.0f;
            } else if (lane == 16) {
                *(float4*)(hs + p * 20 + 16) = make_float4(px, py, pz, 0.0f);
            }
        }
        __syncwarp();

        // ================= layer 0 forward (packed over k) =================
        u64 z0p[PB][4];
        #pragma unroll
        for (int p = 0; p < PB; p++) {
            z0p[p][0] = 0ull; z0p[p][1] = 0ull; z0p[p][2] = 0ull; z0p[p][3] = 0ull;
        }
        #pragma unroll
        for (int kc = 0; kc < 5; kc++) {
            const float* wb = W0kp + kc * 512 + (j0 << 1);
            ulonglong2 wA  = *(const ulonglong2*)(wb);
            ulonglong2 wA2 = *(const ulonglong2*)(wb + 4);
            ulonglong2 wB  = *(const ulonglong2*)(wb + 256);
            ulonglong2 wB2 = *(const ulonglong2*)(wb + 260);
            #pragma unroll
            for (int p = 0; p < PB; p++) {
                ulonglong2 av = *(const ulonglong2*)(hs + p * 20 + kc * 4);
                ffma2(z0p[p][0], wA.x,  av.x);
                ffma2(z0p[p][1], wA.y,  av.x);
                ffma2(z0p[p][2], wA2.x, av.x);
                ffma2(z0p[p][3], wA2.y, av.x);
                ffma2(z0p[p][0], wB.x,  av.y);
                ffma2(z0p[p][1], wB.y,  av.y);
                ffma2(z0p[p][2], wB2.x, av.y);
                ffma2(z0p[p][3], wB2.y, av.y);
            }
        }
        float c0r[PB][4];
        #pragma unroll
        for (int p = 0; p < PB; p++) {
            float4 s;
            float za = hadd2(z0p[p][0]) + b0a[0];
            float zb = hadd2(z0p[p][1]) + b0a[1];
            float zc = hadd2(z0p[p][2]) + b0a[2];
            float zd = hadd2(z0p[p][3]) + b0a[3];
            __sincosf(30.0f * za, &s.x, &c0r[p][0]);
            __sincosf(30.0f * zb, &s.y, &c0r[p][1]);
            __sincosf(30.0f * zc, &s.z, &c0r[p][2]);
            __sincosf(30.0f * zd, &s.w, &c0r[p][3]);
            *(float4*)(buf + p * 128 + j0) = s;
        }
        __syncwarp();

        // ================= layer 1 forward (packed over k) =================
        u64 z1p[PB][4];
        #pragma unroll
        for (int p = 0; p < PB; p++) {
            z1p[p][0] = 0ull; z1p[p][1] = 0ull; z1p[p][2] = 0ull; z1p[p][3] = 0ull;
        }
        #pragma unroll 2
        for (int kc = 0; kc < 32; kc++) {
            const float* wb = W1kp + kc * 512 + (j0 << 1);
            ulonglong2 wA  = *(const ulonglong2*)(wb);
            ulonglong2 wA2 = *(const ulonglong2*)(wb + 4);
            ulonglong2 wB  = *(const ulonglong2*)(wb + 256);
            ulonglong2 wB2 = *(const ulonglong2*)(wb + 260);
            #pragma unroll
            for (int p = 0; p < PB; p++) {
                ulonglong2 av = *(const ulonglong2*)(buf + p * 128 + kc * 4);
                ffma2(z1p[p][0], wA.x,  av.x);
                ffma2(z1p[p][1], wA.y,  av.x);
                ffma2(z1p[p][2], wA2.x, av.x);
                ffma2(z1p[p][3], wA2.y, av.x);
                ffma2(z1p[p][0], wB.x,  av.y);
                ffma2(z1p[p][1], wB.y,  av.y);
                ffma2(z1p[p][2], wB2.x, av.y);
                ffma2(z1p[p][3], wB2.y, av.y);
            }
        }
        __syncwarp();   // all a0 reads done before cos1 overwrites buf

        // ================= head + cos1 stage =================
        float sdf[PB];
        #pragma unroll
        for (int p = 0; p < PB; p++) {
            float s1[4], c1[4];
            float za = hadd2(z1p[p][0]) + b1a[0];
            float zb = hadd2(z1p[p][1]) + b1a[1];
            float zc = hadd2(z1p[p][2]) + b1a[2];
            float zd = hadd2(z1p[p][3]) + b1a[3];
            __sincosf(30.0f * za, &s1[0], &c1[0]);
            __sincosf(30.0f * zb, &s1[1], &c1[1]);
            __sincosf(30.0f * zc, &s1[2], &c1[2]);
            __sincosf(30.0f * zd, &s1[3], &c1[3]);
            float sp = woa[0]*s1[0] + woa[1]*s1[1] + woa[2]*s1[2] + woa[3]*s1[3];
            #pragma unroll
            for (int m = 16; m; m >>= 1) sp += shx(sp, m);
            sdf[p] = sp + bo_r;
            // raw cos only: 30*Wo folded into W1jp at preload
            *(float4*)(buf + p * 128 + j0) = make_float4(c1[0], c1[1], c1[2], c1[3]);
        }
        __syncwarp();

        // ================= backward through W1 (packed over j) =================
        u64 g0p[PB][4];
        #pragma unroll
        for (int p = 0; p < PB; p++) {
            g0p[p][0] = 0ull; g0p[p][1] = 0ull; g0p[p][2] = 0ull; g0p[p][3] = 0ull;
        }
        #pragma unroll 2
        for (int jc = 0; jc < 32; jc++) {
            const float* wb = W1jp + jc * 512 + (j0 << 1);
            ulonglong2 wA  = *(const ulonglong2*)(wb);
            ulonglong2 wA2 = *(const ulonglong2*)(wb + 4);
            ulonglong2 wB  = *(const ulonglong2*)(wb + 256);
            ulonglong2 wB2 = *(const ulonglong2*)(wb + 260);
            #pragma unroll
            for (int p = 0; p < PB; p++) {
                ulonglong2 dv = *(const ulonglong2*)(buf + p * 128 + jc * 4);
                ffma2(g0p[p][0], wA.x,  dv.x);
                ffma2(g0p[p][1], wA.y,  dv.x);
                ffma2(g0p[p][2], wA2.x, dv.x);
                ffma2(g0p[p][3], wA2.y, dv.x);
                ffma2(g0p[p][0], wB.x,  dv.y);
                ffma2(g0p[p][1], wB.y,  dv.y);
                ffma2(g0p[p][2], wB2.x, dv.y);
                ffma2(g0p[p][3], wB2.y, dv.y);
            }
        }
        // d0 = g0 * cos(30 z0)   (both 30-factors pre-folded into weights)
        float d0[PB][4];
        #pragma unroll
        for (int p = 0; p < PB; p++) {
            d0[p][0] = hadd2(g0p[p][0]) * c0r[p][0];
            d0[p][1] = hadd2(g0p[p][1]) * c0r[p][1];
            d0[p][2] = hadd2(g0p[p][2]) * c0r[p][2];
            d0[p][3] = hadd2(g0p[p][3]) * c0r[p][3];
        }

        // ===== backward through W0 fused with gradient dot (float4 dE bcasts) =====
        float gx[PB], gy[PB], gz[PB];
        #pragma unroll
        for (int p = 0; p < PB; p++) { gx[p] = 0.f; gy[p] = 0.f; gz[p] = 0.f; }

        #pragma unroll
        for (int ic = 0; ic < 4; ic++) {          // 4 embedding channels per chunk
            float4 w4_0 = *(const float4*)(W0T + (4*ic+0) * 128 + j0);
            float4 w4_1 = *(const float4*)(W0T + (4*ic+1) * 128 + j0);
            float4 w4_2 = *(const float4*)(W0T + (4*ic+2) * 128 + j0);
            float4 w4_3 = *(const float4*)(W0T + (4*ic+3) * 128 + j0);
            #pragma unroll
            for (int p = 0; p < PB; p++) {
                float t0 = w4_0.x*d0[p][0] + w4_0.y*d0[p][1] + w4_0.z*d0[p][2] + w4_0.w*d0[p][3];
                float t1 = w4_1.x*d0[p][0] + w4_1.y*d0[p][1] + w4_1.z*d0[p][2] + w4_1.w*d0[p][3];
                float t2 = w4_2.x*d0[p][0] + w4_2.y*d0[p][1] + w4_2.z*d0[p][2] + w4_2.w*d0[p][3];
                float t3 = w4_3.x*d0[p][0] + w4_3.y*d0[p][1] + w4_3.z*d0[p][2] + w4_3.w*d0[p][3];
                float4 dx4 = *(const float4*)(dEs + p * 48 + 4*ic);
                float4 dy4 = *(const float4*)(dEs + p * 48 + 16 + 4*ic);
                float4 dz4 = *(const float4*)(dEs + p * 48 + 32 + 4*ic);
                gx[p] = fmaf(t0,dx4.x, fmaf(t1,dx4.y, fmaf(t2,dx4.z, fmaf(t3,dx4.w, gx[p]))));
                gy[p] = fmaf(t0,dy4.x, fmaf(t1,dy4.y, fmaf(t2,dy4.z, fmaf(t3,dy4.w, gy[p]))));
                gz[p] = fmaf(t0,dz4.x, fmaf(t1,dz4.y, fmaf(t2,dz4.z, fmaf(t3,dz4.w, gz[p]))));
            }
        }
        {   // direct position inputs i = 16,17,18
            float4 wx4 = *(const float4*)(W0T + 16 * 128 + j0);
            float4 wy4 = *(const float4*)(W0T + 17 * 128 + j0);
            float4 wz4 = *(const float4*)(W0T + 18 * 128 + j0);
            #pragma unroll
            for (int p = 0; p < PB; p++) {
                gx[p] += wx4.x*d0[p][0] + wx4.y*d0[p][1] + wx4.z*d0[p][2] + wx4.w*d0[p][3];
                gy[p] += wy4.x*d0[p][0] + wy4.y*d0[p][1] + wy4.z*d0[p][2] + wy4.w*d0[p][3];
                gz[p] += wz4.x*d0[p][0] + wz4.y*d0[p][1] + wz4.z*d0[p][2] + wz4.w*d0[p][3];
            }
        }
        #pragma unroll
        for (int p = 0; p < PB; p++) {
            #pragma unroll
            for (int m = 16; m; m >>= 1) {
                gx[p] += shx(gx[p], m);
                gy[p] += shx(gy[p], m);
                gz[p] += shx(gz[p], m);
            }
        }

        if (lane == 0) {
            #pragma unroll
            for (int p = 0; p < PB; p++) {
                int n = n0 + p;
                if (n < n_pts) {
                    out[n] = sdf[p];
                    float* go = out + n_pts + 3 * n;
                    go[0] = gx[p]; go[1] = gy[p]; go[2] = gz[p];
                }
            }
        }
        __syncwarp();
    }
}

extern "C" void kernel_launch(void* const* d_in, const int* in_sizes, int n_in,
                              void* d_out, int out_size) {
    const float* pos  = (const float*)d_in[0];
    const float* grid = (const float*)d_in[1];
    const float* W0   = (const float*)d_in[2];
    const float* b0   = (const float*)d_in[3];
    const float* W1   = (const float*)d_in[4];
    const float* b1   = (const float*)d_in[5];
    const float* Wo   = (const float*)d_in[6];
    const float* bo   = (const float*)d_in[7];
    int n_pts = in_sizes[0] / 3;

    size_t smem = (size_t)SMEM_FLOATS * sizeof(float);
    cudaFuncSetAttribute(neural_sdf_kernel,
                         cudaFuncAttributeMaxDynamicSharedMemorySize, (int)smem);
    neural_sdf_kernel<<<148, THREADS, smem>>>(pos, grid, W0, b0, W1, b1, Wo, bo,
                                              (float*)d_out, n_pts);
}

// round 7
// speedup vs baseline: 1.0663x; 1.0663x over previous
#include <cuda_runtime.h>
#include <math.h>

#define THREADS 384
#define NWARP 12
#define PB 8

typedef unsigned long long u64;

// shared layout (floats)
#define OFF_W1KP 0          // [64][128][2]  fwd:  {W1[j][2k2], W1[j][2k2+1]}
#define OFF_W1JP 16384      // [64][128][2]  bwd:  {30*Wo[j]*W1[j][k]} pairs over j
#define OFF_W0KP 32768      // [10][128][2]  fwd L0 (input 19 zero-padded to 20)
#define OFF_W0T  35328      // [19][128]     bwd-fused, pre-scaled by 30
#define OFF_B0   37760
#define OFF_B1   37888
#define OFF_WO   38016
#define OFF_STAGE 38144
#define WARP_STAGE 1568     // buf 1024 | hs 160 | dEs 384
#define SMEM_FLOATS (OFF_STAGE + NWARP * WARP_STAGE)

__device__ __forceinline__ float shx(float v, int m) {
    return __shfl_xor_sync(0xFFFFFFFFu, v, m);
}
__device__ __forceinline__ void ffma2(u64 &d, u64 a, u64 b) {
    asm("fma.rn.f32x2 %0, %1, %2, %0;" : "+l"(d) : "l"(a), "l"(b));
}
__device__ __forceinline__ float hadd2(u64 v) {
    return __uint_as_float((unsigned)v) + __uint_as_float((unsigned)(v >> 32));
}

__global__ void __launch_bounds__(THREADS, 1)
neural_sdf_kernel(const float* __restrict__ pos,
                  const float* __restrict__ grid,
                  const float* __restrict__ W0g,
                  const float* __restrict__ b0g,
                  const float* __restrict__ W1g,
                  const float* __restrict__ b1g,
                  const float* __restrict__ Wog,
                  const float* __restrict__ bog,
                  float* __restrict__ out,
                  int n_pts)
{
    extern __shared__ float sm[];
    float* W1kp = sm + OFF_W1KP;
    float* W1jp = sm + OFF_W1JP;
    float* W0kp = sm + OFF_W0KP;
    float* W0T  = sm + OFF_W0T;
    float* b0s  = sm + OFF_B0;
    float* b1s  = sm + OFF_B1;
    float* Wos  = sm + OFF_WO;

    const int tid = threadIdx.x;

    // ---- cooperative weight preload ----
    for (int idx = tid; idx < 16384; idx += THREADS) {
        int hi = idx >> 8, rem = idx & 255, m = rem >> 1, c = rem & 1;
        // forward: W1kp[k2][j][c] = W1[j][2*k2+c]
        W1kp[idx] = W1g[m * 128 + (hi * 2 + c)];
        // backward: W1jp[j2][k][c] = 30*Wo[j]*W1[j][k],  j = 2*hi+c
        int j = hi * 2 + c;
        W1jp[idx] = 30.0f * Wog[j] * W1g[j * 128 + m];
    }
    for (int idx = tid; idx < 2560; idx += THREADS) {
        int i2 = idx >> 8, rem = idx & 255, j = rem >> 1, c = rem & 1;
        int i = i2 * 2 + c;
        W0kp[idx] = (i < 19) ? W0g[j * 19 + i] : 0.0f;
    }
    for (int idx = tid; idx < 128 * 19; idx += THREADS) {
        int j = idx / 19;
        int i = idx - j * 19;
        W0T[(i << 7) + j] = 30.0f * W0g[idx];   // layer-0 derivative 30 folded in
    }
    if (tid < 128) {
        b0s[tid] = b0g[tid];
        b1s[tid] = b1g[tid];
        Wos[tid] = Wog[tid];
    }
    __syncthreads();

    const int w    = tid >> 5;
    const int lane = tid & 31;
    float* buf = sm + OFF_STAGE + w * WARP_STAGE;  // a0 then cos1 [p][128]
    float* hs  = buf + PB * 128;                    // [p][20]
    float* dEs = hs + PB * 20;                      // [p][48]: dx16|dy16|dz16

    const int e    = lane & 15;
    const int half = lane >> 4;
    const int j0   = lane << 2;

    float b0a[4], b1a[4], woa[4];
    *(float4*)b0a = *(const float4*)(b0s + j0);
    *(float4*)b1a = *(const float4*)(b1s + j0);
    *(float4*)woa = *(const float4*)(Wos + j0);
    const float bo_r = __ldg(bog);

    const int gw = blockIdx.x * NWARP + w;
    const int nw = gridDim.x * NWARP;

    for (int n0 = gw * PB; n0 < n_pts; n0 += nw * PB) {

        // ================= gather: PB points =================
        #pragma unroll
        for (int p = 0; p < PB; p++) {
            int n = n0 + p;
            int nc = (n < n_pts) ? n : (n_pts - 1);
            float px = fmaf(__ldg(pos + 3 * nc + 0), 0.5f, 0.5f);
            float py = fmaf(__ldg(pos + 3 * nc + 1), 0.5f, 0.5f);
            float pz = fmaf(__ldg(pos + 3 * nc + 2), 0.5f, 0.5f);
            float xx = px * 127.0f, xy = py * 127.0f, xz = pz * 127.0f;
            int ix = min(126, max(0, (int)floorf(xx)));
            int iy = min(126, max(0, (int)floorf(xy)));
            int iz = min(126, max(0, (int)floorf(xz)));
            float fx = xx - (float)ix;
            float fy = xy - (float)iy;
            float fz = xz - (float)iz;
            int base = ((ix << 7) + iy) * 128 + iz;

            float emb = 0.f, dex = 0.f, dey = 0.f, dez = 0.f;
            #pragma unroll
            for (int cc = 0; cc < 4; cc++) {
                int c  = (half << 2) + cc;
                int dx = (c >> 2) & 1, dy = (c >> 1) & 1, dz = c & 1;
                float wx = dx ? fx : 1.0f - fx;
                float wy = dy ? fy : 1.0f - fy;
                float wz = dz ? fz : 1.0f - fz;
                int gi = base + (dx << 14) + (dy << 7) + dz;
                float g = __ldg(grid + (gi << 4) + e);
                float wyz = wy * wz, wxz = wx * wz, wxy = wx * wy;
                emb = fmaf(g, wx * wyz, emb);
                float gyz = g * wyz, gxz = g * wxz, gxy = g * wxy;
                dex += dx ? gyz : -gyz;
                dey += dy ? gxz : -gxz;
                dez += dz ? gxy : -gxy;
            }
            emb += shx(emb, 16);
            dex += shx(dex, 16);
            dey += shx(dey, 16);
            dez += shx(dez, 16);

            if (lane < 16) {
                hs[p * 20 + e]       = emb;
                dEs[p * 48 + e]      = dex * 127.0f;
                dEs[p * 48 + 16 + e] = dey * 127.0f;
                dEs[p * 48 + 32 + e] = dez * 127.0f;
            } else if (lane == 16) {
                *(float4*)(hs + p * 20 + 16) = make_float4(px, py, pz, 0.0f);
            }
        }
        __syncwarp();

        // ================= layer 0 forward (packed over k) =================
        u64 z0p[PB][4];
        #pragma unroll
        for (int p = 0; p < PB; p++) {
            z0p[p][0] = 0ull; z0p[p][1] = 0ull; z0p[p][2] = 0ull; z0p[p][3] = 0ull;
        }
        #pragma unroll
        for (int kc = 0; kc < 5; kc++) {
            const float* wb = W0kp + kc * 512 + (j0 << 1);
            ulonglong2 wA  = *(const ulonglong2*)(wb);
            ulonglong2 wA2 = *(const ulonglong2*)(wb + 4);
            ulonglong2 wB  = *(const ulonglong2*)(wb + 256);
            ulonglong2 wB2 = *(const ulonglong2*)(wb + 260);
            #pragma unroll
            for (int p = 0; p < PB; p++) {
                ulonglong2 av = *(const ulonglong2*)(hs + p * 20 + kc * 4);
                ffma2(z0p[p][0], wA.x,  av.x);
                ffma2(z0p[p][1], wA.y,  av.x);
                ffma2(z0p[p][2], wA2.x, av.x);
                ffma2(z0p[p][3], wA2.y, av.x);
                ffma2(z0p[p][0], wB.x,  av.y);
                ffma2(z0p[p][1], wB.y,  av.y);
                ffma2(z0p[p][2], wB2.x, av.y);
                ffma2(z0p[p][3], wB2.y, av.y);
            }
        }
        float c0r[PB][4];
        #pragma unroll
        for (int p = 0; p < PB; p++) {
            float4 s;
            float za = hadd2(z0p[p][0]) + b0a[0];
            float zb = hadd2(z0p[p][1]) + b0a[1];
            float zc = hadd2(z0p[p][2]) + b0a[2];
            float zd = hadd2(z0p[p][3]) + b0a[3];
            __sincosf(30.0f * za, &s.x, &c0r[p][0]);
            __sincosf(30.0f * zb, &s.y, &c0r[p][1]);
            __sincosf(30.0f * zc, &s.z, &c0r[p][2]);
            __sincosf(30.0f * zd, &s.w, &c0r[p][3]);
            *(float4*)(buf + p * 128 + j0) = s;
        }
        __syncwarp();

        // ================= layer 1 forward (packed over k) =================
        u64 z1p[PB][4];
        #pragma unroll
        for (int p = 0; p < PB; p++) {
            z1p[p][0] = 0ull; z1p[p][1] = 0ull; z1p[p][2] = 0ull; z1p[p][3] = 0ull;
        }
        #pragma unroll 2
        for (int kc = 0; kc < 32; kc++) {
            const float* wb = W1kp + kc * 512 + (j0 << 1);
            ulonglong2 wA  = *(const ulonglong2*)(wb);
            ulonglong2 wA2 = *(const ulonglong2*)(wb + 4);
            ulonglong2 wB  = *(const ulonglong2*)(wb + 256);
            ulonglong2 wB2 = *(const ulonglong2*)(wb + 260);
            #pragma unroll
            for (int p = 0; p < PB; p++) {
                ulonglong2 av = *(const ulonglong2*)(buf + p * 128 + kc * 4);
                ffma2(z1p[p][0], wA.x,  av.x);
                ffma2(z1p[p][1], wA.y,  av.x);
                ffma2(z1p[p][2], wA2.x, av.x);
                ffma2(z1p[p][3], wA2.y, av.x);
                ffma2(z1p[p][0], wB.x,  av.y);
                ffma2(z1p[p][1], wB.y,  av.y);
                ffma2(z1p[p][2], wB2.x, av.y);
                ffma2(z1p[p][3], wB2.y, av.y);
            }
        }
        __syncwarp();   // all a0 reads done before cos1 overwrites buf

        // ================= head + cos1 stage =================
        float sdf[PB];
        #pragma unroll
        for (int p = 0; p < PB; p++) {
            float s1[4], c1[4];
            float za = hadd2(z1p[p][0]) + b1a[0];
            float zb = hadd2(z1p[p][1]) + b1a[1];
            float zc = hadd2(z1p[p][2]) + b1a[2];
            float zd = hadd2(z1p[p][3]) + b1a[3];
            __sincosf(30.0f * za, &s1[0], &c1[0]);
            __sincosf(30.0f * zb, &s1[1], &c1[1]);
            __sincosf(30.0f * zc, &s1[2], &c1[2]);
            __sincosf(30.0f * zd, &s1[3], &c1[3]);
            float sp = woa[0]*s1[0] + woa[1]*s1[1] + woa[2]*s1[2] + woa[3]*s1[3];
            #pragma unroll
            for (int m = 16; m; m >>= 1) sp += shx(sp, m);
            sdf[p] = sp + bo_r;
            // raw cos only: 30*Wo folded into W1jp at preload
            *(float4*)(buf + p * 128 + j0) = make_float4(c1[0], c1[1], c1[2], c1[3]);
        }
        __syncwarp();

        // ================= backward through W1 (packed over j) =================
        u64 g0p[PB][4];
        #pragma unroll
        for (int p = 0; p < PB; p++) {
            g0p[p][0] = 0ull; g0p[p][1] = 0ull; g0p[p][2] = 0ull; g0p[p][3] = 0ull;
        }
        #pragma unroll 2
        for (int jc = 0; jc < 32; jc++) {
            const float* wb = W1jp + jc * 512 + (j0 << 1);
            ulonglong2 wA  = *(const ulonglong2*)(wb);
            ulonglong2 wA2 = *(const ulonglong2*)(wb + 4);
            ulonglong2 wB  = *(const ulonglong2*)(wb + 256);
            ulonglong2 wB2 = *(const ulonglong2*)(wb + 260);
            #pragma unroll
            for (int p = 0; p < PB; p++) {
                ulonglong2 dv = *(const ulonglong2*)(buf + p * 128 + jc * 4);
                ffma2(g0p[p][0], wA.x,  dv.x);
                ffma2(g0p[p][1], wA.y,  dv.x);
                ffma2(g0p[p][2], wA2.x, dv.x);
                ffma2(g0p[p][3], wA2.y, dv.x);
                ffma2(g0p[p][0], wB.x,  dv.y);
                ffma2(g0p[p][1], wB.y,  dv.y);
                ffma2(g0p[p][2], wB2.x, dv.y);
                ffma2(g0p[p][3], wB2.y, dv.y);
            }
        }
        // d0 = g0 * cos(30 z0)   (both 30-factors pre-folded into weights)
        float d0[PB][4];
        #pragma unroll
        for (int p = 0; p < PB; p++) {
            d0[p][0] = hadd2(g0p[p][0]) * c0r[p][0];
            d0[p][1] = hadd2(g0p[p][1]) * c0r[p][1];
            d0[p][2] = hadd2(g0p[p][2]) * c0r[p][2];
            d0[p][3] = hadd2(g0p[p][3]) * c0r[p][3];
        }

        // ===== backward through W0 fused with gradient dot (float4 dE bcasts) =====
        float gx[PB], gy[PB], gz[PB];
        #pragma unroll
        for (int p = 0; p < PB; p++) { gx[p] = 0.f; gy[p] = 0.f; gz[p] = 0.f; }

        #pragma unroll
        for (int ic = 0; ic < 4; ic++) {          // 4 embedding channels per chunk
            float4 w4_0 = *(const float4*)(W0T + (4*ic+0) * 128 + j0);
            float4 w4_1 = *(const float4*)(W0T + (4*ic+1) * 128 + j0);
            float4 w4_2 = *(const float4*)(W0T + (4*ic+2) * 128 + j0);
            float4 w4_3 = *(const float4*)(W0T + (4*ic+3) * 128 + j0);
            #pragma unroll
            for (int p = 0; p < PB; p++) {
                float t0 = w4_0.x*d0[p][0] + w4_0.y*d0[p][1] + w4_0.z*d0[p][2] + w4_0.w*d0[p][3];
                float t1 = w4_1.x*d0[p][0] + w4_1.y*d0[p][1] + w4_1.z*d0[p][2] + w4_1.w*d0[p][3];
                float t2 = w4_2.x*d0[p][0] + w4_2.y*d0[p][1] + w4_2.z*d0[p][2] + w4_2.w*d0[p][3];
                float t3 = w4_3.x*d0[p][0] + w4_3.y*d0[p][1] + w4_3.z*d0[p][2] + w4_3.w*d0[p][3];
                float4 dx4 = *(const float4*)(dEs + p * 48 + 4*ic);
                float4 dy4 = *(const float4*)(dEs + p * 48 + 16 + 4*ic);
                float4 dz4 = *(const float4*)(dEs + p * 48 + 32 + 4*ic);
                gx[p] = fmaf(t0,dx4.x, fmaf(t1,dx4.y, fmaf(t2,dx4.z, fmaf(t3,dx4.w, gx[p]))));
                gy[p] = fmaf(t0,dy4.x, fmaf(t1,dy4.y, fmaf(t2,dy4.z, fmaf(t3,dy4.w, gy[p]))));
                gz[p] = fmaf(t0,dz4.x, fmaf(t1,dz4.y, fmaf(t2,dz4.z, fmaf(t3,dz4.w, gz[p]))));
            }
        }
        {   // direct position inputs i = 16,17,18
            float4 wx4 = *(const float4*)(W0T + 16 * 128 + j0);
            float4 wy4 = *(const float4*)(W0T + 17 * 128 + j0);
            float4 wz4 = *(const float4*)(W0T + 18 * 128 + j0);
            #pragma unroll
            for (int p = 0; p < PB; p++) {
                gx[p] += wx4.x*d0[p][0] + wx4.y*d0[p][1] + wx4.z*d0[p][2] + wx4.w*d0[p][3];
                gy[p] += wy4.x*d0[p][0] + wy4.y*d0[p][1] + wy4.z*d0[p][2] + wy4.w*d0[p][3];
                gz[p] += wz4.x*d0[p][0] + wz4.y*d0[p][1] + wz4.z*d0[p][2] + wz4.w*d0[p][3];
            }
        }
        #pragma unroll
        for (int p = 0; p < PB; p++) {
            #pragma unroll
            for (int m = 16; m; m >>= 1) {
                gx[p] += shx(gx[p], m);
                gy[p] += shx(gy[p], m);
                gz[p] += shx(gz[p], m);
            }
        }

        if (lane == 0) {
            #pragma unroll
            for (int p = 0; p < PB; p++) {
                int n = n0 + p;
                if (n < n_pts) {
                    out[n] = sdf[p];
                    float* go = out + n_pts + 3 * n;
                    go[0] = gx[p]; go[1] = gy[p]; go[2] = gz[p];
                }
            }
        }
        __syncwarp();
    }
}

extern "C" void kernel_launch(void* const* d_in, const int* in_sizes, int n_in,
                              void* d_out, int out_size) {
    const float* pos  = (const float*)d_in[0];
    const float* grid = (const float*)d_in[1];
    const float* W0   = (const float*)d_in[2];
    const float* b0   = (const float*)d_in[3];
    const float* W1   = (const float*)d_in[4];
    const float* b1   = (const float*)d_in[5];
    const float* Wo   = (const float*)d_in[6];
    const float* bo   = (const float*)d_in[7];
    int n_pts = in_sizes[0] / 3;

    size_t smem = (size_t)SMEM_FLOATS * sizeof(float);
    cudaFuncSetAttribute(neural_sdf_kernel,
                         cudaFuncAttributeMaxDynamicSharedMemorySize, (int)smem);
    neural_sdf_kernel<<<148, THREADS, smem>>>(pos, grid, W0, b0, W1, b1, Wo, bo,
                                              (float*)d_out, n_pts);
}

// round 9
// speedup vs baseline: 2.2871x; 2.1449x over previous
#include <cuda_runtime.h>
#include <cuda_bf16.h>
#include <math.h>
#include <stdint.h>

#define THREADS 256

// ---- smem byte offsets ----
#define O_F1F_H 0          // W1 fwd frags hi  [kt8][nt16][lane32][2] u32
#define O_F1F_L 32768
#define O_F1B_H 65536      // W1 bwd frags
#define O_F1B_L 98304
#define O_F0F_H 131072     // W0 fwd frags [kt2][nt16][lane][2]
#define O_F0F_L 139264
#define O_F0G_H 147456     // W0 grad frags [kt8][nt4][lane][2]
#define O_F0G_L 155648
#define O_HS    163840     // float [128][34]
#define O_DE    181248     // float [48][132]
#define O_B0    206592
#define O_B1    207104
#define O_WO    207616
#define O_BO    208128
#define SMEM_BYTES 208136

#define MMA(acc, a, b) asm volatile( \
    "mma.sync.aligned.m16n8k16.row.col.f32.bf16.bf16.f32 " \
    "{%0,%1,%2,%3}, {%4,%5,%6,%7}, {%8,%9}, {%0,%1,%2,%3};" \
    : "+f"((acc)[0]), "+f"((acc)[1]), "+f"((acc)[2]), "+f"((acc)[3]) \
    : "r"((a)[0]), "r"((a)[1]), "r"((a)[2]), "r"((a)[3]), \
      "r"((b).x), "r"((b).y))

__device__ __forceinline__ unsigned packbf(float a, float b) {
    unsigned ua = __bfloat16_as_ushort(__float2bfloat16(a));
    unsigned ub = __bfloat16_as_ushort(__float2bfloat16(b));
    return ua | (ub << 16);
}
__device__ __forceinline__ void split2u(float a, float b, unsigned &hi, unsigned &lo) {
    __nv_bfloat16 ah = __float2bfloat16(a), bh = __float2bfloat16(b);
    hi = (unsigned)__bfloat16_as_ushort(ah) | ((unsigned)__bfloat16_as_ushort(bh) << 16);
    lo = packbf(a - __bfloat162float(ah), b - __bfloat162float(bh));
}
__device__ __forceinline__ float bflo(unsigned u) {
    return __bfloat162float(__ushort_as_bfloat16((unsigned short)(u & 0xFFFFu)));
}
__device__ __forceinline__ float bfhi(unsigned u) {
    return __bfloat162float(__ushort_as_bfloat16((unsigned short)(u >> 16)));
}

__global__ void __launch_bounds__(THREADS, 1)
neural_sdf_mma(const float* __restrict__ pos,
               const float* __restrict__ grid,
               const float* __restrict__ W0g,
               const float* __restrict__ b0g,
               const float* __restrict__ W1g,
               const float* __restrict__ b1g,
               const float* __restrict__ Wog,
               const float* __restrict__ bog,
               float* __restrict__ out,
               int n_pts)
{
    extern __shared__ char smc[];
    unsigned* F1F_H = (unsigned*)(smc + O_F1F_H);
    unsigned* F1F_L = (unsigned*)(smc + O_F1F_L);
    unsigned* F1B_H = (unsigned*)(smc + O_F1B_H);
    unsigned* F1B_L = (unsigned*)(smc + O_F1B_L);
    unsigned* F0F_H = (unsigned*)(smc + O_F0F_H);
    unsigned* F0F_L = (unsigned*)(smc + O_F0F_L);
    unsigned* F0G_H = (unsigned*)(smc + O_F0G_H);
    unsigned* F0G_L = (unsigned*)(smc + O_F0G_L);
    float* hs  = (float*)(smc + O_HS);
    float* dEs = (float*)(smc + O_DE);
    float* b0s = (float*)(smc + O_B0);
    float* b1s = (float*)(smc + O_B1);
    float* wos = (float*)(smc + O_WO);
    float* bos = (float*)(smc + O_BO);

    const int tid  = threadIdx.x;
    const int wid  = tid >> 5;
    const int lane = tid & 31;
    const int g    = lane >> 2;     // group id (row within fragment)
    const int t    = lane & 3;      // thread in group (col pair)

    // ---------------- weight fragment pre-pack ----------------
    for (int idx = tid; idx < 8192; idx += THREADS) {
        int kt = idx >> 10;
        int nt = (idx >> 6) & 15;
        int l  = (idx >> 1) & 31;
        int r  = idx & 1;
        int gg = l >> 2, tt = l & 3;
        int kk = kt * 16 + r * 8 + 2 * tt;
        int nn = nt * 8 + gg;
        unsigned hi, lo;
        split2u(W1g[nn * 128 + kk], W1g[nn * 128 + kk + 1], hi, lo);
        F1F_H[idx] = hi; F1F_L[idx] = lo;
        split2u(W1g[kk * 128 + nn], W1g[(kk + 1) * 128 + nn], hi, lo);
        F1B_H[idx] = hi; F1B_L[idx] = lo;
    }
    // W0 fwd: B[i][n=j] = W0[j][i], i>=19 zero. kt2 x nt16. hi+lo.
    for (int idx = tid; idx < 2048; idx += THREADS) {
        int kt = idx >> 10;
        int nt = (idx >> 6) & 15;
        int l  = (idx >> 1) & 31;
        int r  = idx & 1;
        int gg = l >> 2, tt = l & 3;
        int i  = kt * 16 + r * 8 + 2 * tt;
        int j  = nt * 8 + gg;
        float v0 = (i     < 19) ? W0g[j * 19 + i]     : 0.0f;
        float v1 = (i + 1 < 19) ? W0g[j * 19 + i + 1] : 0.0f;
        unsigned hi, lo;
        split2u(v0, v1, hi, lo);
        F0F_H[idx] = hi; F0F_L[idx] = lo;
    }
    // W0 grad: B[j][n=i] = W0[j][i], i>=19 zero. kt8 x nt4. hi+lo.
    for (int idx = tid; idx < 2048; idx += THREADS) {
        int kt = idx >> 8;
        int nt = (idx >> 6) & 3;
        int l  = (idx >> 1) & 31;
        int r  = idx & 1;
        int gg = l >> 2, tt = l & 3;
        int jr = kt * 16 + r * 8 + 2 * tt;
        int i  = nt * 8 + gg;
        float v0 = (i < 19) ? W0g[jr * 19 + i]       : 0.0f;
        float v1 = (i < 19) ? W0g[(jr + 1) * 19 + i] : 0.0f;
        unsigned hi, lo;
        split2u(v0, v1, hi, lo);
        F0G_H[idx] = hi; F0G_L[idx] = lo;
    }
    if (tid < 128) {
        b0s[tid] = b0g[tid];
        b1s[tid] = b1g[tid];
        wos[tid] = Wog[tid];
    }
    if (tid == 0) bos[0] = bog[0];
    __syncthreads();

    const int mb = wid * 16;
    const int e    = lane & 15;
    const int half = lane >> 4;
    const float boV = bos[0];
    const int ntiles = (n_pts + 127) >> 7;

    for (int tile = blockIdx.x; tile < ntiles; tile += gridDim.x) {

        // ================= gather 16 points (whole warp per point) ===========
        for (int it = 0; it < 16; it++) {
            int prow = mb + it;
            int n  = tile * 128 + prow;
            int nc = (n < n_pts) ? n : (n_pts - 1);
            float px = fmaf(__ldg(pos + 3 * nc + 0), 0.5f, 0.5f);
            float py = fmaf(__ldg(pos + 3 * nc + 1), 0.5f, 0.5f);
            float pz = fmaf(__ldg(pos + 3 * nc + 2), 0.5f, 0.5f);
            float xx = px * 127.0f, xy = py * 127.0f, xz = pz * 127.0f;
            int ix = min(126, max(0, (int)floorf(xx)));
            int iy = min(126, max(0, (int)floorf(xy)));
            int iz = min(126, max(0, (int)floorf(xz)));
            float fx = xx - (float)ix;
            float fy = xy - (float)iy;
            float fz = xz - (float)iz;
            int base = ((ix << 7) + iy) * 128 + iz;

            float emb = 0.f, dex = 0.f, dey = 0.f, dez = 0.f;
            #pragma unroll
            for (int cc = 0; cc < 4; cc++) {
                int c  = (half << 2) + cc;
                int dx = (c >> 2) & 1, dy = (c >> 1) & 1, dz = c & 1;
                float wx = dx ? fx : 1.0f - fx;
                float wy = dy ? fy : 1.0f - fy;
                float wz = dz ? fz : 1.0f - fz;
                int gi = base + (dx << 14) + (dy << 7) + dz;
                float gv = __ldg(grid + (gi << 4) + e);
                float wyz = wy * wz, wxz = wx * wz, wxy = wx * wy;
                emb = fmaf(gv, wx * wyz, emb);
                float gyz = gv * wyz, gxz = gv * wxz, gxy = gv * wxy;
                dex += dx ? gyz : -gyz;
                dey += dy ? gxz : -gxz;
                dez += dz ? gxy : -gxy;
            }
            emb += __shfl_xor_sync(0xFFFFFFFFu, emb, 16);
            dex += __shfl_xor_sync(0xFFFFFFFFu, dex, 16);
            dey += __shfl_xor_sync(0xFFFFFFFFu, dey, 16);
            dez += __shfl_xor_sync(0xFFFFFFFFu, dez, 16);

            if (lane < 16) {
                hs[prow * 34 + e] = emb;
                dEs[(e)      * 132 + prow] = dex * 127.0f;
                dEs[(16 + e) * 132 + prow] = dey * 127.0f;
                dEs[(32 + e) * 132 + prow] = dez * 127.0f;
            } else if (lane == 16) {
                hs[prow * 34 + 16] = px;
                hs[prow * 34 + 17] = py;
                hs[prow * 34 + 18] = pz;
            } else if (lane >= 19) {
                hs[prow * 34 + lane] = 0.0f;
            }
        }
        __syncwarp();

        // ================= L0 A fragments from hs ===========================
        unsigned ah0[2][4], al0[2][4];
        {
            const float* hr0 = hs + (mb + g) * 34;
            const float* hr1 = hs + (mb + g + 8) * 34;
            #pragma unroll
            for (int kt = 0; kt < 2; kt++) {
                int c = kt * 16 + 2 * t;
                float2 v0 = *(const float2*)(hr0 + c);
                float2 v1 = *(const float2*)(hr1 + c);
                float2 v2 = *(const float2*)(hr0 + c + 8);
                float2 v3 = *(const float2*)(hr1 + c + 8);
                split2u(v0.x, v0.y, ah0[kt][0], al0[kt][0]);
                split2u(v1.x, v1.y, ah0[kt][1], al0[kt][1]);
                split2u(v2.x, v2.y, ah0[kt][2], al0[kt][2]);
                split2u(v3.x, v3.y, ah0[kt][3], al0[kt][3]);
            }
        }

        float acc[16][4];
        #pragma unroll
        for (int nt = 0; nt < 16; nt++) {
            acc[nt][0] = 0.f; acc[nt][1] = 0.f; acc[nt][2] = 0.f; acc[nt][3] = 0.f;
        }

        // ================= GEMM L0: z0 = in @ W0^T (3 passes) ================
        #pragma unroll
        for (int kt = 0; kt < 2; kt++) {
            #pragma unroll
            for (int nt = 0; nt < 16; nt++) {
                int fo = (((kt << 4) + nt) << 6) + (lane << 1);
                uint2 bh = *(const uint2*)(F0F_H + fo);
                MMA(acc[nt], ah0[kt], bh);
                MMA(acc[nt], al0[kt], bh);
                uint2 bl = *(const uint2*)(F0F_L + fo);
                MMA(acc[nt], ah0[kt], bl);
            }
        }

        // ======== L0 epilogue: sin -> A frags; cos kept as bf16 hi+lo ========
        unsigned a1h[8][4], a1l[8][4], cosh0[32], cosl0[32];
        #pragma unroll
        for (int nt = 0; nt < 16; nt++) {
            int n0 = nt * 8;
            float bb0 = b0s[n0 + 2 * t], bb1 = b0s[n0 + 2 * t + 1];
            float s00, c00, s01, c01, s02, c02, s03, c03;
            __sincosf(30.0f * (acc[nt][0] + bb0), &s00, &c00);
            __sincosf(30.0f * (acc[nt][1] + bb1), &s01, &c01);
            __sincosf(30.0f * (acc[nt][2] + bb0), &s02, &c02);
            __sincosf(30.0f * (acc[nt][3] + bb1), &s03, &c03);
            split2u(c00, c01, cosh0[nt * 2],     cosl0[nt * 2]);
            split2u(c02, c03, cosh0[nt * 2 + 1], cosl0[nt * 2 + 1]);
            int kt2 = nt >> 1;
            int hf  = (nt & 1) << 1;
            split2u(s00, s01, a1h[kt2][hf],     a1l[kt2][hf]);
            split2u(s02, s03, a1h[kt2][hf + 1], a1l[kt2][hf + 1]);
        }

        // ================= GEMM L1: z1 = a0 @ W1^T (3 passes) ================
        #pragma unroll
        for (int nt = 0; nt < 16; nt++) {
            acc[nt][0] = 0.f; acc[nt][1] = 0.f; acc[nt][2] = 0.f; acc[nt][3] = 0.f;
        }
        #pragma unroll
        for (int kt = 0; kt < 8; kt++) {
            #pragma unroll
            for (int nt = 0; nt < 16; nt++) {
                int fo = (((kt << 4) + nt) << 6) + (lane << 1);
                uint2 bh = *(const uint2*)(F1F_H + fo);
                MMA(acc[nt], a1h[kt], bh);
                MMA(acc[nt], a1l[kt], bh);
                uint2 bl = *(const uint2*)(F1F_L + fo);
                MMA(acc[nt], a1h[kt], bl);
            }
        }

        // ================= L1 epilogue: sdf + d1 frags =======================
        float sp = 0.f, sp8 = 0.f;
        #pragma unroll
        for (int nt = 0; nt < 16; nt++) {
            int n0 = nt * 8;
            float bb0 = b1s[n0 + 2 * t], bb1 = b1s[n0 + 2 * t + 1];
            float w0 = wos[n0 + 2 * t],  w1 = wos[n0 + 2 * t + 1];
            float s00, c00, s01, c01, s02, c02, s03, c03;
            __sincosf(30.0f * (acc[nt][0] + bb0), &s00, &c00);
            __sincosf(30.0f * (acc[nt][1] + bb1), &s01, &c01);
            __sincosf(30.0f * (acc[nt][2] + bb0), &s02, &c02);
            __sincosf(30.0f * (acc[nt][3] + bb1), &s03, &c03);
            sp  += w0 * s00 + w1 * s01;
            sp8 += w0 * s02 + w1 * s03;
            float d00 = 30.0f * w0 * c00, d01 = 30.0f * w1 * c01;
            float d02 = 30.0f * w0 * c02, d03 = 30.0f * w1 * c03;
            int kt2 = nt >> 1;
            int hf  = (nt & 1) << 1;
            split2u(d00, d01, a1h[kt2][hf],     a1l[kt2][hf]);
            split2u(d02, d03, a1h[kt2][hf + 1], a1l[kt2][hf + 1]);
        }
        sp  += __shfl_xor_sync(0xFFFFFFFFu, sp, 1);
        sp  += __shfl_xor_sync(0xFFFFFFFFu, sp, 2);
        sp8 += __shfl_xor_sync(0xFFFFFFFFu, sp8, 1);
        sp8 += __shfl_xor_sync(0xFFFFFFFFu, sp8, 2);
        int p0g = tile * 128 + mb + g;
        int p1g = p0g + 8;
        if (t == 0) {
            if (p0g < n_pts) out[p0g] = sp + boV;
            if (p1g < n_pts) out[p1g] = sp8 + boV;
        }

        // ================= GEMM BW1: g0 = d1 @ W1 (3 passes) =================
        #pragma unroll
        for (int nt = 0; nt < 16; nt++) {
            acc[nt][0] = 0.f; acc[nt][1] = 0.f; acc[nt][2] = 0.f; acc[nt][3] = 0.f;
        }
        #pragma unroll
        for (int kt = 0; kt < 8; kt++) {
            #pragma unroll
            for (int nt = 0; nt < 16; nt++) {
                int fo = (((kt << 4) + nt) << 6) + (lane << 1);
                uint2 bh = *(const uint2*)(F1B_H + fo);
                MMA(acc[nt], a1h[kt], bh);
                MMA(acc[nt], a1l[kt], bh);
                uint2 bl = *(const uint2*)(F1B_L + fo);
                MMA(acc[nt], a1h[kt], bl);
            }
        }

        // ====== BW1 epilogue: d0 = g0 * 30*cos0 (cos0 = hi+lo) -> frags ======
        #pragma unroll
        for (int nt = 0; nt < 16; nt++) {
            unsigned ch0 = cosh0[nt * 2],     cl0 = cosl0[nt * 2];
            unsigned ch1 = cosh0[nt * 2 + 1], cl1 = cosl0[nt * 2 + 1];
            float cv00 = bflo(ch0) + bflo(cl0);
            float cv01 = bfhi(ch0) + bfhi(cl0);
            float cv02 = bflo(ch1) + bflo(cl1);
            float cv03 = bfhi(ch1) + bfhi(cl1);
            float d00 = acc[nt][0] * 30.0f * cv00;
            float d01 = acc[nt][1] * 30.0f * cv01;
            float d02 = acc[nt][2] * 30.0f * cv02;
            float d03 = acc[nt][3] * 30.0f * cv03;
            int kt2 = nt >> 1;
            int hf  = (nt & 1) << 1;
            split2u(d00, d01, a1h[kt2][hf],     a1l[kt2][hf]);
            split2u(d02, d03, a1h[kt2][hf + 1], a1l[kt2][hf + 1]);
        }

        // ================= GEMM GRAD: gh = d0 @ W0 (n=24, 3 passes) ==========
        float acc3[3][4];
        #pragma unroll
        for (int nt = 0; nt < 3; nt++) {
            acc3[nt][0] = 0.f; acc3[nt][1] = 0.f; acc3[nt][2] = 0.f; acc3[nt][3] = 0.f;
        }
        #pragma unroll
        for (int kt = 0; kt < 8; kt++) {
            #pragma unroll
            for (int nt = 0; nt < 3; nt++) {
                int fo = (((kt << 2) + nt) << 6) + (lane << 1);
                uint2 bh = *(const uint2*)(F0G_H + fo);
                MMA(acc3[nt], a1h[kt], bh);
                MMA(acc3[nt], a1l[kt], bh);
                uint2 bl = *(const uint2*)(F0G_L + fo);
                MMA(acc3[nt], a1h[kt], bl);
            }
        }

        // ================= gradient epilogue =================================
        {
            float gx = 0.f, gy = 0.f, gz = 0.f, gx8 = 0.f, gy8 = 0.f, gz8 = 0.f;
            int pr0 = mb + g, pr1 = pr0 + 8;
            #pragma unroll
            for (int nt = 0; nt < 2; nt++) {
                int i0 = nt * 8 + 2 * t;
                float c0 = acc3[nt][0], c1 = acc3[nt][1];
                float c2 = acc3[nt][2], c3 = acc3[nt][3];
                gx  += c0 * dEs[(i0)      * 132 + pr0] + c1 * dEs[(i0 + 1)      * 132 + pr0];
                gx8 += c2 * dEs[(i0)      * 132 + pr1] + c3 * dEs[(i0 + 1)      * 132 + pr1];
                gy  += c0 * dEs[(16 + i0) * 132 + pr0] + c1 * dEs[(17 + i0)     * 132 + pr0];
                gy8 += c2 * dEs[(16 + i0) * 132 + pr1] + c3 * dEs[(17 + i0)     * 132 + pr1];
                gz  += c0 * dEs[(32 + i0) * 132 + pr0] + c1 * dEs[(33 + i0)     * 132 + pr0];
                gz8 += c2 * dEs[(32 + i0) * 132 + pr1] + c3 * dEs[(33 + i0)     * 132 + pr1];
            }
            if (t == 0) { gx += acc3[2][0]; gy += acc3[2][1]; gx8 += acc3[2][2]; gy8 += acc3[2][3]; }
            if (t == 1) { gz += acc3[2][0]; gz8 += acc3[2][2]; }
            #pragma unroll
            for (int m = 1; m <= 2; m <<= 1) {
                gx  += __shfl_xor_sync(0xFFFFFFFFu, gx, m);
                gy  += __shfl_xor_sync(0xFFFFFFFFu, gy, m);
                gz  += __shfl_xor_sync(0xFFFFFFFFu, gz, m);
                gx8 += __shfl_xor_sync(0xFFFFFFFFu, gx8, m);
                gy8 += __shfl_xor_sync(0xFFFFFFFFu, gy8, m);
                gz8 += __shfl_xor_sync(0xFFFFFFFFu, gz8, m);
            }
            if (t == 0) {
                if (p0g < n_pts) {
                    float* go = out + n_pts + 3 * p0g;
                    go[0] = gx; go[1] = gy; go[2] = gz;
                }
                if (p1g < n_pts) {
                    float* go = out + n_pts + 3 * p1g;
                    go[0] = gx8; go[1] = gy8; go[2] = gz8;
                }
            }
        }
        __syncwarp();
    }
}

extern "C" void kernel_launch(void* const* d_in, const int* in_sizes, int n_in,
                              void* d_out, int out_size) {
    const float* pos  = (const float*)d_in[0];
    const float* grid = (const float*)d_in[1];
    const float* W0   = (const float*)d_in[2];
    const float* b0   = (const float*)d_in[3];
    const float* W1   = (const float*)d_in[4];
    const float* b1   = (const float*)d_in[5];
    const float* Wo   = (const float*)d_in[6];
    const float* bo   = (const float*)d_in[7];
    int n_pts = in_sizes[0] / 3;

    cudaFuncSetAttribute(neural_sdf_mma,
                         cudaFuncAttributeMaxDynamicSharedMemorySize, SMEM_BYTES);
    neural_sdf_mma<<<148, THREADS, SMEM_BYTES>>>(pos, grid, W0, b0, W1, b1, Wo, bo,
                                                 (float*)d_out, n_pts);
}